// round 12
// baseline (speedup 1.0000x reference)
#include <cuda_runtime.h>
#include <cstdint>

#define B_ 64
#define J_ 25
#define V_ 50000
#define BPB 32          // batches per fk block

#define TM 128          // vertices per CTA tile
#define TN 64           // N cols per CTA tile (= 4 batches * 16)
#define TK 32           // K padded (25 joints -> 32)
#define MT ((V_ + TM - 1) / TM)      // 391
#define NT ((B_ * 16) / TN)          // 16

#define ABLK 68         // A per-thread block stride (64 payload + 4 pad words)
#define BBLK 34         // B per-thread block stride (32 payload + 2 pad words)
#define AWORDS (64 * ABLK)   // 4352
#define BWORDS (64 * BBLK)   // 2176
#define SST 68               // S row stride (conflict-free LDS.128 reads)

// Device globals (no allocation allowed). Zero-initialized: padded K cols of
// g_Tp (j = 25..31) are never written and stay 0.
__device__ float g_Tp[B_ * 16 * TK];   // tf32-rounded DeltaT, [n][j] n=b*16+r*4+c
__device__ float g_Tbar[B_ * 12];      // fp32 per-batch mean transform rows

__device__ __forceinline__ uint32_t f2tf32(float f) {
    uint32_t u;
    asm("cvt.rna.tf32.f32 %0, %1;" : "=r"(u) : "f"(f));
    return u;
}

// ---------------------------------------------------------------------------
// FK kernel (unchanged from R11, validated): emits joint_out, g_Tbar, and
// tf32-rounded DeltaT = T - Tbar in K-major g_Tp.
// ---------------------------------------------------------------------------
__global__ __launch_bounds__(1024)
void fk_kernel(const float* __restrict__ je,
               const float* __restrict__ lp,
               const float* __restrict__ sc,
               const float* __restrict__ gpi,
               const int* __restrict__ parents,
               float* __restrict__ joint_out) {
    __shared__ float ls[BPB * J_ * 12];
    __shared__ float gpis[J_ * 16];
    __shared__ int   par[J_];

    int tid = threadIdx.x;
    int bbase = blockIdx.x * BPB;

    if (tid < J_ * 16) gpis[tid] = gpi[tid];
    if (tid < J_) par[tid] = parents[tid];

    for (int idx = tid; idx < BPB * J_; idx += blockDim.x) {
        int j = idx % J_;
        int gidx = bbase * J_ + idx;
        float ex = je[gidx*3+0], ey = je[gidx*3+1], ez = je[gidx*3+2];
        float sx, cx, sy, cy, sz, cz;
        sincosf(ex, &sx, &cx);
        sincosf(ey, &sy, &cy);
        sincosf(ez, &sz, &cz);
        float R00 = cz*cy, R01 = cz*sy*sx - sz*cx, R02 = cz*sy*cx + sz*sx;
        float R10 = sz*cy, R11 = sz*sy*sx + cz*cx, R12 = sz*sy*cx - cz*sx;
        float R20 = -sy,   R21 = cy*sx,            R22 = cy*cx;
        const float* L0 = lp + j*16;
        float* out = ls + idx*12;
        #pragma unroll
        for (int r = 0; r < 3; ++r) {
            float a0 = L0[r*4+0], a1 = L0[r*4+1], a2 = L0[r*4+2];
            out[r*4+0] = a0*R00 + a1*R10 + a2*R20;
            out[r*4+1] = a0*R01 + a1*R11 + a2*R21;
            out[r*4+2] = a0*R02 + a1*R12 + a2*R22;
            out[r*4+3] = L0[r*4+3] + sc[j*3+r];
        }
    }

    __syncthreads();

    if (tid >= BPB * 3) return;
    int bl = tid / 3, r = tid % 3;
    int b = bbase + bl;

    float Grow[J_][4];
    float pr0 = 0.f, pr1 = 0.f, pr2 = 0.f, pr3 = 0.f;
    int prevj = -2;
    float s0 = 0.f, s1 = 0.f, s2 = 0.f, s3 = 0.f;

    for (int j = 0; j < J_; ++j) {
        int pj = par[j];
        float g0, g1, g2, g3;
        if (pj < 0) {
            g0 = (r == 0) ? 1.f : 0.f;
            g1 = (r == 1) ? 1.f : 0.f;
            g2 = (r == 2) ? 1.f : 0.f;
            g3 = 0.f;
        } else {
            float p0, p1, p2, p3;
            if (pj == prevj) { p0 = pr0; p1 = pr1; p2 = pr2; p3 = pr3; }
            else { p0 = Grow[pj][0]; p1 = Grow[pj][1]; p2 = Grow[pj][2]; p3 = Grow[pj][3]; }
            const float* L = ls + (bl*J_ + j) * 12;
            g0 = p0*L[0] + p1*L[4] + p2*L[8];
            g1 = p0*L[1] + p1*L[5] + p2*L[9];
            g2 = p0*L[2] + p1*L[6] + p2*L[10];
            g3 = p0*L[3] + p1*L[7] + p2*L[11] + p3;
        }
        Grow[j][0] = g0; Grow[j][1] = g1; Grow[j][2] = g2; Grow[j][3] = g3;
        pr0 = g0; pr1 = g1; pr2 = g2; pr3 = g3; prevj = j;

        const float* P = gpis + j*16;
        s0 += g0*P[0] + g1*P[4] + g2*P[8];
        s1 += g0*P[1] + g1*P[5] + g2*P[9];
        s2 += g0*P[2] + g1*P[6] + g2*P[10];
        s3 += g0*P[3] + g1*P[7] + g2*P[11] + g3;
        joint_out[(b*J_ + j)*3 + r] = g3;
    }

    const float inv = 1.0f / (float)J_;
    float m0 = s0*inv, m1 = s1*inv, m2 = s2*inv, m3 = s3*inv;
    g_Tbar[b*12 + r*4 + 0] = m0;
    g_Tbar[b*12 + r*4 + 1] = m1;
    g_Tbar[b*12 + r*4 + 2] = m2;
    g_Tbar[b*12 + r*4 + 3] = m3;

    int nbase = (b * 16 + r * 4);
    for (int j = 0; j < J_; ++j) {
        float g0 = Grow[j][0], g1 = Grow[j][1], g2 = Grow[j][2], g3 = Grow[j][3];
        const float* P = gpis + j*16;
        float t0 = g0*P[0] + g1*P[4] + g2*P[8]          - m0;
        float t1 = g0*P[1] + g1*P[5] + g2*P[9]          - m1;
        float t2 = g0*P[2] + g1*P[6] + g2*P[10]         - m2;
        float t3 = g0*P[3] + g1*P[7] + g2*P[11] + g3    - m3;
        g_Tp[(nbase + 0) * TK + j] = __uint_as_float(f2tf32(t0));
        g_Tp[(nbase + 1) * TK + j] = __uint_as_float(f2tf32(t1));
        g_Tp[(nbase + 2) * TK + j] = __uint_as_float(f2tf32(t2));
        g_Tp[(nbase + 3) * TK + j] = __uint_as_float(f2tf32(t3));
    }
}

// ---------------------------------------------------------------------------
// mma.sync m16n8k8 tf32 (baseline PTX, sm_80+)
// ---------------------------------------------------------------------------
__device__ __forceinline__ void mma_tf32(float* d, const uint32_t* a,
                                         const uint32_t* b) {
    asm volatile(
        "mma.sync.aligned.m16n8k8.row.col.f32.tf32.tf32.f32 "
        "{%0,%1,%2,%3}, {%4,%5,%6,%7}, {%8,%9}, {%0,%1,%2,%3};"
        : "+f"(d[0]), "+f"(d[1]), "+f"(d[2]), "+f"(d[3])
        : "r"(a[0]), "r"(a[1]), "r"(a[2]), "r"(a[3]), "r"(b[0]), "r"(b[1]));
}

// ---------------------------------------------------------------------------
// Skinning via warp tf32 GEMM, fragment-linear staging (conflict-free LDS).
// CTA: 128 thr (4 warps), tile 128 vtx x 64 N (4 batches), warp tile m64n32.
// A layout: per (h,gid,tig) thread-block of 68 words; quad [A0..A3] for
//   (ks,mi) contiguous at offset (ks*4+mi)*4.  A0..A3 = rows (gid,gid+8) x
//   k (tig, tig+4) of the m16n8k8 A fragment.
// B layout: per (nh,gid,tig) block of 34 words; pair [B0,B1] at (ks*4+ni)*2.
// Epilogue: accs -> S smem (stride 68, conflict-free LDS.128), one phase.
// ---------------------------------------------------------------------------
__global__ __launch_bounds__(128, 4)
void skin_mma_kernel(const float* __restrict__ vtx,
                     const float* __restrict__ W,
                     const float* __restrict__ pc,
                     const float* __restrict__ ic,
                     float* __restrict__ mesh_out) {
    // union: stage A (4352 w) + B (2176 w) = 6528 w  vs  S (128*68 = 8704 w)
    __shared__ __align__(16) float usm[TM * SST];     // 34816 B
    __shared__ float tbars[4 * 16];
    __shared__ float vts[TM * 3];

    float* wsA = usm;
    float* wsB = usm + AWORDS;
    float* S   = usm;

    int tid = threadIdx.x;
    int wid = tid >> 5, lane = tid & 31;
    int gid = lane >> 2, tig = lane & 3;
    int v0 = blockIdx.x * TM;
    int bbase = blockIdx.y * 4;
    int nv = min(TM, V_ - v0);

    // ---- zero A (covers K pad + M tail), load tbars + vts ----
    float4 z4 = make_float4(0.f, 0.f, 0.f, 0.f);
    for (int i = tid; i < AWORDS / 4; i += 128)
        reinterpret_cast<float4*>(wsA)[i] = z4;
    if (tid < 48) tbars[(tid / 12) * 16 + (tid % 12)] = g_Tbar[bbase * 12 + tid];
    for (int i = tid; i < nv * 3; i += 128) vts[i] = vtx[v0 * 3 + i];
    __syncthreads();

    // ---- stage A: W[v0+v][j] -> fragment-linear, tf32-rounded ----
    for (int i = tid; i < nv * J_; i += 128) {
        int v = i / J_;
        int j = i - v * J_;
        int h = v >> 6, m = v & 63;
        int mi = m >> 4, rowhalf = (m >> 3) & 1, agid = m & 7;
        int ks = j >> 3, khalf = (j >> 2) & 1, atig = j & 3;
        int addr = ((h * 8 + agid) * 4 + atig) * ABLK
                 + (ks * 4 + mi) * 4 + (khalf * 2 + rowhalf);
        wsA[addr] = __uint_as_float(f2tf32(W[(size_t)v0 * J_ + i]));
    }
    // ---- stage B: g_Tp slice [64 n][32 j] -> fragment-linear ----
    const float* tsrc = g_Tp + bbase * 16 * TK;
    for (int i = tid; i < TN * TK; i += 128) {
        int n = i >> 5, j = i & 31;
        int nh = n >> 5, m = n & 31;
        int ni = m >> 3, bgid = m & 7;
        int ks = j >> 3, khalf = (j >> 2) & 1, btig = j & 3;
        int addr = ((nh * 8 + bgid) * 4 + btig) * BBLK
                 + (ks * 4 + ni) * 2 + khalf;
        wsB[addr] = tsrc[i];
    }
    __syncthreads();

    // ---- GEMM: warp tile m64n32, 64 HMMA ----
    int h  = wid & 1;          // m half: wm = h*64
    int nh = wid >> 1;         // n half: wn = nh*32
    const float* blkA = wsA + ((h * 8 + gid) * 4 + tig) * ABLK;
    const float* blkB = wsB + ((nh * 8 + gid) * 4 + tig) * BBLK;

    float acc[4][4][4];
    #pragma unroll
    for (int mi = 0; mi < 4; ++mi)
        #pragma unroll
        for (int ni = 0; ni < 4; ++ni)
            #pragma unroll
            for (int k = 0; k < 4; ++k) acc[mi][ni][k] = 0.f;

    #pragma unroll
    for (int ks = 0; ks < 4; ++ks) {
        uint32_t A[4][4], Bf[4][2];
        #pragma unroll
        for (int mi = 0; mi < 4; ++mi) {
            float4 a4 = *reinterpret_cast<const float4*>(blkA + (ks * 4 + mi) * 4);
            A[mi][0] = __float_as_uint(a4.x);
            A[mi][1] = __float_as_uint(a4.y);
            A[mi][2] = __float_as_uint(a4.z);
            A[mi][3] = __float_as_uint(a4.w);
        }
        #pragma unroll
        for (int ni = 0; ni < 4; ++ni) {
            float2 b2 = *reinterpret_cast<const float2*>(blkB + (ks * 4 + ni) * 2);
            Bf[ni][0] = __float_as_uint(b2.x);
            Bf[ni][1] = __float_as_uint(b2.y);
        }
        #pragma unroll
        for (int mi = 0; mi < 4; ++mi)
            #pragma unroll
            for (int ni = 0; ni < 4; ++ni)
                mma_tf32(acc[mi][ni], A[mi], Bf[ni]);
    }
    __syncthreads();   // stage buffers dead; region becomes S

    // ---- accs -> S ----
    {
        int wm = h * 64, wn = nh * 32;
        #pragma unroll
        for (int mi = 0; mi < 4; ++mi) {
            int row = wm + mi * 16 + gid;
            #pragma unroll
            for (int ni = 0; ni < 4; ++ni) {
                int col = wn + ni * 8 + 2 * tig;
                *reinterpret_cast<float2*>(&S[row * SST + col]) =
                    make_float2(acc[mi][ni][0], acc[mi][ni][1]);
                *reinterpret_cast<float2*>(&S[(row + 8) * SST + col]) =
                    make_float2(acc[mi][ni][2], acc[mi][ni][3]);
            }
        }
    }
    __syncthreads();

    // ---- epilogue: thread = vertex, 4 batches; all gmem loads batched ----
    int v = v0 + tid;
    if (v < V_) {
        int o0 = (bbase * V_ + v) * 3;
        const int sb = V_ * 3;
        float P[4][3];
        #pragma unroll
        for (int bl = 0; bl < 4; ++bl) {
            int o = o0 + bl * sb;
            P[bl][0] = pc[o+0] + ic[o+0];
            P[bl][1] = pc[o+1] + ic[o+1];
            P[bl][2] = pc[o+2] + ic[o+2];
        }
        float vx = vts[tid*3+0], vy = vts[tid*3+1], vz = vts[tid*3+2];
        #pragma unroll
        for (int bl = 0; bl < 4; ++bl) {
            const float4* Sr = reinterpret_cast<const float4*>(&S[tid * SST + bl * 16]);
            float4 m0 = Sr[0], m1 = Sr[1], m2 = Sr[2];
            const float4* Tb = reinterpret_cast<const float4*>(&tbars[bl * 16]);
            float4 t0 = Tb[0], t1 = Tb[1], t2 = Tb[2];
            float px = vx + P[bl][0], py = vy + P[bl][1], pz = vz + P[bl][2];
            int o = o0 + bl * sb;
            mesh_out[o+0] = fmaf(m0.x+t0.x, px, fmaf(m0.y+t0.y, py,
                            fmaf(m0.z+t0.z, pz, m0.w+t0.w)));
            mesh_out[o+1] = fmaf(m1.x+t1.x, px, fmaf(m1.y+t1.y, py,
                            fmaf(m1.z+t1.z, pz, m1.w+t1.w)));
            mesh_out[o+2] = fmaf(m2.x+t2.x, px, fmaf(m2.y+t2.y, py,
                            fmaf(m2.z+t2.z, pz, m2.w+t2.w)));
        }
    }
}

// ---------------------------------------------------------------------------
extern "C" void kernel_launch(void* const* d_in, const int* in_sizes, int n_in,
                              void* d_out, int out_size) {
    const float* joint_euler = (const float*)d_in[0];
    const float* vtx         = (const float*)d_in[1];
    const float* W           = (const float*)d_in[2];
    const float* local_pose  = (const float*)d_in[3];
    const float* gpi         = (const float*)d_in[4];
    const float* sc          = (const float*)d_in[5];
    const float* pc          = (const float*)d_in[6];
    const float* ic          = (const float*)d_in[7];
    const int*   parents     = (const int*)d_in[8];
    float* out = (float*)d_out;

    fk_kernel<<<B_ / BPB, 1024>>>(joint_euler, local_pose, sc, gpi, parents, out);
    dim3 grid(MT, NT);
    skin_mma_kernel<<<grid, 128>>>(vtx, W, pc, ic, out + B_*J_*3);
}

// round 13
// speedup vs baseline: 1.8438x; 1.8438x over previous
#include <cuda_runtime.h>

#define B_ 64
#define J_ 25
#define V_ 50000
#define VT 128          // threads per skin block
#define VPT 2           // vertices per thread (consecutive; V_%2==0)
#define VT2 (VT*VPT)    // 256 vertices per block
#define NB 8            // batches per skin block
#define NPAIR (NB/2)
#define WSTR 258        // transposed-weight row stride (even -> 8B-aligned rows)
#define BPB 32          // batches per fk block

// Scratch (device global; no allocation allowed)
__device__ float g_T[B_*J_*12];   // per-(b,j) skinning transform (3x4 row-major)

// ---------------------------------------------------------------------------
// FK kernel: 2 blocks x 1024 threads, 32 batches per block. Locals in smem,
// 96 threads run the sequential chain with smem-only reads.
// ---------------------------------------------------------------------------
__global__ __launch_bounds__(1024)
void fk_kernel(const float* __restrict__ je,
               const float* __restrict__ lp,
               const float* __restrict__ sc,
               const float* __restrict__ gpi,
               const int* __restrict__ parents,
               float* __restrict__ joint_out) {
    __shared__ float ls[BPB * J_ * 12];
    __shared__ float gpis[J_ * 16];
    __shared__ int   par[J_];

    int tid = threadIdx.x;
    int bbase = blockIdx.x * BPB;

    if (tid < J_ * 16) gpis[tid] = gpi[tid];
    if (tid < J_) par[tid] = parents[tid];

    for (int idx = tid; idx < BPB * J_; idx += blockDim.x) {
        int j = idx % J_;
        int gidx = bbase * J_ + idx;
        float ex = je[gidx*3+0], ey = je[gidx*3+1], ez = je[gidx*3+2];
        float sx, cx, sy, cy, sz, cz;
        sincosf(ex, &sx, &cx);
        sincosf(ey, &sy, &cy);
        sincosf(ez, &sz, &cz);
        float R00 = cz*cy, R01 = cz*sy*sx - sz*cx, R02 = cz*sy*cx + sz*sx;
        float R10 = sz*cy, R11 = sz*sy*sx + cz*cx, R12 = sz*sy*cx - cz*sx;
        float R20 = -sy,   R21 = cy*sx,            R22 = cy*cx;
        const float* L0 = lp + j*16;
        float* out = ls + idx*12;
        #pragma unroll
        for (int r = 0; r < 3; ++r) {
            float a0 = L0[r*4+0], a1 = L0[r*4+1], a2 = L0[r*4+2];
            out[r*4+0] = a0*R00 + a1*R10 + a2*R20;
            out[r*4+1] = a0*R01 + a1*R11 + a2*R21;
            out[r*4+2] = a0*R02 + a1*R12 + a2*R22;
            out[r*4+3] = L0[r*4+3] + sc[j*3+r];
        }
    }

    __syncthreads();

    if (tid >= BPB * 3) return;
    int bl = tid / 3, r = tid % 3;
    int b = bbase + bl;

    float Grow[J_][4];
    float pr0 = 0.f, pr1 = 0.f, pr2 = 0.f, pr3 = 0.f;
    int prevj = -2;
    for (int j = 0; j < J_; ++j) {
        int pj = par[j];
        float g0, g1, g2, g3;
        if (pj < 0) {
            g0 = (r == 0) ? 1.f : 0.f;
            g1 = (r == 1) ? 1.f : 0.f;
            g2 = (r == 2) ? 1.f : 0.f;
            g3 = 0.f;
        } else {
            float p0, p1, p2, p3;
            if (pj == prevj) { p0 = pr0; p1 = pr1; p2 = pr2; p3 = pr3; }
            else { p0 = Grow[pj][0]; p1 = Grow[pj][1]; p2 = Grow[pj][2]; p3 = Grow[pj][3]; }
            const float* L = ls + (bl*J_ + j) * 12;
            g0 = p0*L[0] + p1*L[4] + p2*L[8];
            g1 = p0*L[1] + p1*L[5] + p2*L[9];
            g2 = p0*L[2] + p1*L[6] + p2*L[10];
            g3 = p0*L[3] + p1*L[7] + p2*L[11] + p3;
        }
        Grow[j][0] = g0; Grow[j][1] = g1; Grow[j][2] = g2; Grow[j][3] = g3;
        pr0 = g0; pr1 = g1; pr2 = g2; pr3 = g3; prevj = j;

        const float* P = gpis + j*16;
        float4 t4;
        t4.x = g0*P[0] + g1*P[4] + g2*P[8];
        t4.y = g0*P[1] + g1*P[5] + g2*P[9];
        t4.z = g0*P[2] + g1*P[6] + g2*P[10];
        t4.w = g0*P[3] + g1*P[7] + g2*P[11] + g3;
        *reinterpret_cast<float4*>(g_T + (b*J_ + j)*12 + r*4) = t4;
        joint_out[(b*J_ + j)*3 + r] = g3;
    }
}

// ---------------------------------------------------------------------------
// f32x2 packed helpers (sm_100+)
// ---------------------------------------------------------------------------
__device__ __forceinline__ unsigned long long pack2(float lo, float hi) {
    unsigned long long d;
    asm("mov.b64 %0, {%1, %2};" : "=l"(d)
        : "r"(__float_as_uint(lo)), "r"(__float_as_uint(hi)));
    return d;
}
__device__ __forceinline__ unsigned long long pack2s(float w) {
    unsigned long long d;
    asm("mov.b64 %0, {%1, %1};" : "=l"(d) : "r"(__float_as_uint(w)));
    return d;
}
__device__ __forceinline__ void unpack2(unsigned long long s, float& lo, float& hi) {
    unsigned int a, b;
    asm("mov.b64 {%0, %1}, %2;" : "=r"(a), "=r"(b) : "l"(s));
    lo = __uint_as_float(a); hi = __uint_as_float(b);
}
__device__ __forceinline__ void fma2acc(unsigned long long& d,
                                        unsigned long long a,
                                        unsigned long long b) {
    asm("fma.rn.f32x2 %0, %1, %2, %0;" : "+l"(d) : "l"(a), "l"(b));
}
__device__ __forceinline__ unsigned long long fma2(unsigned long long a,
                                                   unsigned long long b,
                                                   unsigned long long c) {
    unsigned long long d;
    asm("fma.rn.f32x2 %0, %1, %2, %3;" : "=l"(d) : "l"(a), "l"(b), "l"(c));
    return d;
}

// ---------------------------------------------------------------------------
// Skinning kernel. R8 shape (128 thr x 2 vtx x 8 batches) at 5 blocks/SM:
// the corrective hoist is dropped (proven neutral R3 vs R8) to fit the
// 102-reg cap of launch_bounds(128,5) WITHOUT spills -> 20 warps/SM fill
// the LDS dependency bubbles of the binding L1 pipe (70.4% -> ~85%).
// All offsets 32-bit.
// ---------------------------------------------------------------------------
__global__ __launch_bounds__(VT, 5)
void skin_kernel(const float* __restrict__ vtx,
                 const float* __restrict__ W,
                 const float* __restrict__ pc,
                 const float* __restrict__ ic,
                 float* __restrict__ mesh_out) {
    __shared__ float ws_t[J_ * WSTR];                     // 25.8 KB, transposed
    __shared__ __align__(16) float2 Ts[NPAIR * J_ * 12];  // 9.6 KB

    int tid = threadIdx.x;
    int v0 = blockIdx.x * VT2;
    int b0base = blockIdx.y * NB;
    int nv = min(VT2, V_ - v0);   // V_%2==0 -> nv%2==0

    // Stage weights transposed: ws_t[j*WSTR + vv] = W[v0+vv][j]
    for (int i = tid; i < nv * J_; i += VT) {
        int vv = i / J_;
        int j  = i - vv * J_;
        ws_t[j * WSTR + vv] = W[(size_t)v0 * J_ + i];
    }
    // Stage T for NB batches, interleaved per batch pair
    for (int i = tid; i < NPAIR * J_ * 12; i += VT) {
        int p = i / (J_ * 12);
        int rem = i - p * (J_ * 12);
        int b0 = b0base + 2 * p;
        Ts[i] = make_float2(g_T[b0 * (J_*12) + rem],
                            g_T[(b0 + 1) * (J_*12) + rem]);
    }
    __syncthreads();

    int lv = VPT * tid;            // local vertex base
    if (lv >= nv) return;          // all-or-nothing (nv%2==0)
    int vA = v0 + lv;
    int vB = vA + 1;

    float vAx = vtx[vA*3+0], vAy = vtx[vA*3+1], vAz = vtx[vA*3+2];
    float vBx = vtx[vB*3+0], vBy = vtx[vB*3+1], vBz = vtx[vB*3+2];

    const int strideB = V_ * 3;                          // 150000
    const int base = b0base * strideB + vA * 3;          // < 9.6M, fits int

    const float* wb = ws_t + lv;

    #pragma unroll 1
    for (int p = 0; p < NPAIR; ++p) {
        int o0 = base + (2 * p) * strideB;   // batch b0: [Ax Ay Az Bx By Bz]
        int o1 = o0 + strideB;               // batch b1

        // ---- blend: M = sum_j w[v][j] * T[pair j] ----
        unsigned long long MA[12], MB[12];
        #pragma unroll
        for (int k = 0; k < 12; ++k) { MA[k] = 0ull; MB[k] = 0ull; }

        const ulonglong2* tb =
            reinterpret_cast<const ulonglong2*>(Ts + p * (J_ * 12));
        #pragma unroll 5
        for (int j = 0; j < J_; ++j) {
            float2 wv = *reinterpret_cast<const float2*>(wb + j * WSTR);
            unsigned long long wA = pack2s(wv.x);
            unsigned long long wB = pack2s(wv.y);
            const ulonglong2* trow = tb + j * 6;   // 12 float2 = 6 x 16B
            #pragma unroll
            for (int m = 0; m < 6; ++m) {
                ulonglong2 q = trow[m];
                fma2acc(MA[2*m],   q.x, wA); fma2acc(MA[2*m+1], q.y, wA);
                fma2acc(MB[2*m],   q.x, wB); fma2acc(MB[2*m+1], q.y, wB);
            }
        }

        // ---- load correctives (after the loop; throughput-bound regime) ----
        float2 pA0 = *(const float2*)(pc + o0);
        float2 pA1 = *(const float2*)(pc + o0 + 2);
        float2 pA2 = *(const float2*)(pc + o0 + 4);
        float2 pB0 = *(const float2*)(pc + o1);
        float2 pB1 = *(const float2*)(pc + o1 + 2);
        float2 pB2 = *(const float2*)(pc + o1 + 4);
        float2 iA0 = *(const float2*)(ic + o0);
        float2 iA1 = *(const float2*)(ic + o0 + 2);
        float2 iA2 = *(const float2*)(ic + o0 + 4);
        float2 iB0 = *(const float2*)(ic + o1);
        float2 iB1 = *(const float2*)(ic + o1 + 2);
        float2 iB2 = *(const float2*)(ic + o1 + 4);

        // ---- pack coords over {b0, b1} ----
        unsigned long long ppxA = pack2(vAx + pA0.x + iA0.x, vAx + pB0.x + iB0.x);
        unsigned long long ppyA = pack2(vAy + pA0.y + iA0.y, vAy + pB0.y + iB0.y);
        unsigned long long ppzA = pack2(vAz + pA1.x + iA1.x, vAz + pB1.x + iB1.x);
        unsigned long long ppxB = pack2(vBx + pA1.y + iA1.y, vBx + pB1.y + iB1.y);
        unsigned long long ppyB = pack2(vBy + pA2.x + iA2.x, vBy + pB2.x + iB2.x);
        unsigned long long ppzB = pack2(vBz + pA2.y + iA2.y, vBz + pB2.y + iB2.y);

        float a0x, a1x, a0y, a1y, a0z, a1z;   // vertex A rows {b0,b1}
        float b0x, b1x, b0y, b1y, b0z, b1z;   // vertex B rows {b0,b1}
        {
            unsigned long long o;
            o = fma2(MA[2], ppzA, MA[3]); o = fma2(MA[1], ppyA, o); o = fma2(MA[0], ppxA, o);
            unpack2(o, a0x, a1x);
            o = fma2(MA[6], ppzA, MA[7]); o = fma2(MA[5], ppyA, o); o = fma2(MA[4], ppxA, o);
            unpack2(o, a0y, a1y);
            o = fma2(MA[10], ppzA, MA[11]); o = fma2(MA[9], ppyA, o); o = fma2(MA[8], ppxA, o);
            unpack2(o, a0z, a1z);
            o = fma2(MB[2], ppzB, MB[3]); o = fma2(MB[1], ppyB, o); o = fma2(MB[0], ppxB, o);
            unpack2(o, b0x, b1x);
            o = fma2(MB[6], ppzB, MB[7]); o = fma2(MB[5], ppyB, o); o = fma2(MB[4], ppxB, o);
            unpack2(o, b0y, b1y);
            o = fma2(MB[10], ppzB, MB[11]); o = fma2(MB[9], ppyB, o); o = fma2(MB[8], ppxB, o);
            unpack2(o, b0z, b1z);
        }

        // ---- store: 6 consecutive floats per batch, 3x STG.64 ----
        *(float2*)(mesh_out + o0)     = make_float2(a0x, a0y);
        *(float2*)(mesh_out + o0 + 2) = make_float2(a0z, b0x);
        *(float2*)(mesh_out + o0 + 4) = make_float2(b0y, b0z);
        *(float2*)(mesh_out + o1)     = make_float2(a1x, a1y);
        *(float2*)(mesh_out + o1 + 2) = make_float2(a1z, b1x);
        *(float2*)(mesh_out + o1 + 4) = make_float2(b1y, b1z);
    }
}

// ---------------------------------------------------------------------------
extern "C" void kernel_launch(void* const* d_in, const int* in_sizes, int n_in,
                              void* d_out, int out_size) {
    const float* joint_euler = (const float*)d_in[0];
    const float* vtx         = (const float*)d_in[1];
    const float* W           = (const float*)d_in[2];
    const float* local_pose  = (const float*)d_in[3];
    const float* gpi         = (const float*)d_in[4];
    const float* sc          = (const float*)d_in[5];
    const float* pc          = (const float*)d_in[6];
    const float* ic          = (const float*)d_in[7];
    const int*   parents     = (const int*)d_in[8];
    float* out = (float*)d_out;

    fk_kernel<<<B_ / BPB, 1024>>>(joint_euler, local_pose, sc, gpi, parents, out);
    dim3 grid((V_ + VT2 - 1) / VT2, B_ / NB);
    skin_kernel<<<grid, VT>>>(vtx, W, pc, ic, out + B_*J_*3);
}